// round 4
// baseline (speedup 1.0000x reference)
#include <cuda_runtime.h>
#include <math.h>

// Problem constants
constexpr int Bc = 32, Sc = 512, Dc = 512, Hc = 8, Lc = 4, FFc = 2048;
constexpr int M = Bc * Sc;          // 16384 token rows
constexpr float SCALE = 0.125f;     // 1/sqrt(64)

// ---------------- scratch (static device memory; no allocations) -------------
__device__ float g_x  [(size_t)M * Dc];
__device__ float g_y  [(size_t)M * Dc];
__device__ float g_qk [(size_t)M * Dc];
__device__ float g_v  [(size_t)M * Dc];
__device__ float g_ctx[(size_t)M * Dc];
__device__ float g_t  [(size_t)M * FFc];

// ---------------- x = in + pos (pos broadcast over batch) --------------------
__global__ void add_pos_kernel(const float* __restrict__ in,
                               const float* __restrict__ pos,
                               float* __restrict__ out, int n4, int sd4)
{
    int i = blockIdx.x * blockDim.x + threadIdx.x;
    if (i < n4) {
        float4 a = ((const float4*)in)[i];
        float4 p = ((const float4*)pos)[i % sd4];
        a.x += p.x; a.y += p.y; a.z += p.z; a.w += p.w;
        ((float4*)out)[i] = a;
    }
}

// ---------------- SGEMM: C = A[M,K] @ W[K,N] + bias (opt ReLU) ---------------
// 128x64 block tile, 256 threads, 8x4 micro-tile, K-step 16.
template<bool RELU>
__global__ __launch_bounds__(256)
void gemm_kernel(const float* __restrict__ A, const float* __restrict__ W,
                 const float* __restrict__ bias, float* __restrict__ C,
                 int N, int K)
{
    __shared__ float As[16][132];   // A transposed: As[k][m]
    __shared__ float Bs[16][68];    // Bs[k][n]

    const int bm = blockIdx.y * 128;
    const int bn = blockIdx.x * 64;
    const int tid = threadIdx.x;
    const int tr = tid >> 4;        // 0..15 -> rows tr*8..+8
    const int tc = tid & 15;        // 0..15 -> cols tc*4..+4

    float acc[8][4];
#pragma unroll
    for (int i = 0; i < 8; i++)
#pragma unroll
        for (int j = 0; j < 4; j++) acc[i][j] = 0.f;

    for (int k0 = 0; k0 < K; k0 += 16) {
        __syncthreads();
        // load A tile 128x16 (512 float4), store transposed
#pragma unroll
        for (int q = 0; q < 2; q++) {
            int idx = tid + q * 256;
            int r = idx >> 2, kq = idx & 3;
            float4 av = *(const float4*)(A + (size_t)(bm + r) * K + k0 + kq * 4);
            As[kq * 4 + 0][r] = av.x;
            As[kq * 4 + 1][r] = av.y;
            As[kq * 4 + 2][r] = av.z;
            As[kq * 4 + 3][r] = av.w;
        }
        // load B tile 16x64 (256 float4)
        {
            int k = tid >> 4, n4 = tid & 15;
            *(float4*)(&Bs[k][n4 * 4]) =
                *(const float4*)(W + (size_t)(k0 + k) * N + bn + n4 * 4);
        }
        __syncthreads();
#pragma unroll
        for (int k = 0; k < 16; k++) {
            float4 a0 = *(float4*)(&As[k][tr * 8]);
            float4 a1 = *(float4*)(&As[k][tr * 8 + 4]);
            float4 bv = *(float4*)(&Bs[k][tc * 4]);
            float a[8] = {a0.x, a0.y, a0.z, a0.w, a1.x, a1.y, a1.z, a1.w};
            float bb[4] = {bv.x, bv.y, bv.z, bv.w};
#pragma unroll
            for (int i = 0; i < 8; i++)
#pragma unroll
                for (int j = 0; j < 4; j++)
                    acc[i][j] += a[i] * bb[j];
        }
    }

    float4 bb = *(const float4*)(bias + bn + tc * 4);
#pragma unroll
    for (int i = 0; i < 8; i++) {
        float4 o;
        o.x = acc[i][0] + bb.x;
        o.y = acc[i][1] + bb.y;
        o.z = acc[i][2] + bb.z;
        o.w = acc[i][3] + bb.w;
        if (RELU) {
            o.x = fmaxf(o.x, 0.f); o.y = fmaxf(o.y, 0.f);
            o.z = fmaxf(o.z, 0.f); o.w = fmaxf(o.w, 0.f);
        }
        *(float4*)(C + (size_t)(bm + tr * 8 + i) * N + bn + tc * 4) = o;
    }
}

// ---------------- fused attention (flash-style) ------------------------------
// One CTA per (b, h, 64-row query tile). Strict-causal (j < i) visibility,
// scores *= SCALE * forget[b, i]. Row i==0 (per sequence) zeroed.
constexpr int ATTN_SMEM = (64 * 68 * 2 + 64 * 65 + 64 * 64 + 64) * 4;

__global__ __launch_bounds__(256)
void attn_kernel(const float* __restrict__ qk, const float* __restrict__ v,
                 const float* __restrict__ forget, float* __restrict__ ctx)
{
    extern __shared__ float sm[];
    float* Qs = sm;                  // [64][68]
    float* Ks = Qs + 64 * 68;        // [64][68]
    float* Ss = Ks + 64 * 68;        // [64][65]
    float* Vs = Ss + 64 * 65;        // [64][64]
    float* Fr = Vs + 64 * 64;        // [64]

    const int tid = threadIdx.x;
    const int it = blockIdx.x;
    const int bh = blockIdx.y;
    const int b = bh >> 3, h = bh & 7;
    const int i0 = it * 64;

    const float* Qbase = qk + ((size_t)b * Sc) * Dc + h * 64;
    const float* Vbase = v  + ((size_t)b * Sc) * Dc + h * 64;

    // load Q tile (64 rows x 64 cols)
#pragma unroll
    for (int q = 0; q < 4; q++) {
        int idx = tid + q * 256;
        int r = idx >> 4, c4 = idx & 15;
        *(float4*)(&Qs[r * 68 + c4 * 4]) =
            *(const float4*)(Qbase + (size_t)(i0 + r) * Dc + c4 * 4);
    }
    if (tid < 64) Fr[tid] = forget[b * Sc + i0 + tid];

    const int tr = tid >> 4, tc = tid & 15;  // score-phase mapping (4x4 tile)
    const int r  = tid >> 2, cg = tid & 3;   // softmax/accum mapping
    float mrow = -3.0e30f, lsum = 0.0f;
    float acc[16];
#pragma unroll
    for (int i = 0; i < 16; i++) acc[i] = 0.f;

    for (int jt = 0; jt <= it; jt++) {
        __syncthreads();   // previous-iteration reads of Ks/Vs/Ss done
#pragma unroll
        for (int q = 0; q < 4; q++) {
            int idx = tid + q * 256;
            int rr = idx >> 4, c4 = idx & 15;
            *(float4*)(&Ks[rr * 68 + c4 * 4]) =
                *(const float4*)(Qbase + (size_t)(jt * 64 + rr) * Dc + c4 * 4);
            *(float4*)(&Vs[rr * 64 + c4 * 4]) =
                *(const float4*)(Vbase + (size_t)(jt * 64 + rr) * Dc + c4 * 4);
        }
        __syncthreads();

        // scores: each thread computes a 4x4 block of S = Q K^T
        float sacc[4][4];
#pragma unroll
        for (int i = 0; i < 4; i++)
#pragma unroll
            for (int j = 0; j < 4; j++) sacc[i][j] = 0.f;
#pragma unroll
        for (int k = 0; k < 64; k += 4) {
            float4 a[4], bb[4];
#pragma unroll
            for (int i = 0; i < 4; i++) a[i]  = *(float4*)(&Qs[(tr * 4 + i) * 68 + k]);
#pragma unroll
            for (int j = 0; j < 4; j++) bb[j] = *(float4*)(&Ks[(tc * 4 + j) * 68 + k]);
#pragma unroll
            for (int i = 0; i < 4; i++)
#pragma unroll
                for (int j = 0; j < 4; j++)
                    sacc[i][j] += a[i].x * bb[j].x + a[i].y * bb[j].y
                                + a[i].z * bb[j].z + a[i].w * bb[j].w;
        }
#pragma unroll
        for (int i = 0; i < 4; i++) {
            int il = tr * 4 + i;
            float f = SCALE * Fr[il];
#pragma unroll
            for (int j = 0; j < 4; j++) {
                int jl = tc * 4 + j;
                float sval = ((jt * 64 + jl) < (i0 + il)) ? sacc[i][j] * f : -1.0e30f;
                Ss[il * 65 + jl] = sval;
            }
        }
        __syncthreads();

        // online softmax + O accumulation (row r, cols cg*16..+16)
        float tmax = -3.0e30f;
#pragma unroll
        for (int j = 0; j < 64; j++) tmax = fmaxf(tmax, Ss[r * 65 + j]);
        float mnew = fmaxf(mrow, tmax);
        float corr = __expf(mrow - mnew);
        lsum *= corr;
#pragma unroll
        for (int i = 0; i < 16; i++) acc[i] *= corr;
#pragma unroll
        for (int j = 0; j < 64; j++) {
            float p = __expf(Ss[r * 65 + j] - mnew);
            lsum += p;
            const float* vrow = &Vs[j * 64 + cg * 16];
#pragma unroll
            for (int q2 = 0; q2 < 4; q2++) {
                float4 vv = *(const float4*)(vrow + q2 * 4);
                acc[q2 * 4 + 0] += p * vv.x;
                acc[q2 * 4 + 1] += p * vv.y;
                acc[q2 * 4 + 2] += p * vv.z;
                acc[q2 * 4 + 3] += p * vv.w;
            }
        }
        mrow = mnew;
    }

    // row 0 of each sequence is zeroed (zero_pad in reference)
    float inv = (i0 + r == 0) ? 0.0f : 1.0f / lsum;
    float* out = ctx + ((size_t)b * Sc + i0 + r) * Dc + h * 64 + cg * 16;
#pragma unroll
    for (int q2 = 0; q2 < 4; q2++) {
        float4 o = make_float4(acc[q2 * 4 + 0] * inv, acc[q2 * 4 + 1] * inv,
                               acc[q2 * 4 + 2] * inv, acc[q2 * 4 + 3] * inv);
        *(float4*)(out + q2 * 4) = o;
    }
}

// ---------------- fused residual + LayerNorm ---------------------------------
__global__ __launch_bounds__(128)
void resid_ln_kernel(const float* __restrict__ x, const float* __restrict__ t,
                     const float* __restrict__ g, const float* __restrict__ b,
                     float* __restrict__ out)
{
    const int row = blockIdx.x;
    const int tid = threadIdx.x;
    float4 xv = *(const float4*)(x + (size_t)row * Dc + tid * 4);
    float4 tv = *(const float4*)(t + (size_t)row * Dc + tid * 4);
    float v0 = xv.x + tv.x, v1 = xv.y + tv.y, v2 = xv.z + tv.z, v3 = xv.w + tv.w;
    float s  = v0 + v1 + v2 + v3;
    float sq = v0 * v0 + v1 * v1 + v2 * v2 + v3 * v3;
#pragma unroll
    for (int o = 16; o; o >>= 1) {
        s  += __shfl_xor_sync(0xffffffffu, s, o);
        sq += __shfl_xor_sync(0xffffffffu, sq, o);
    }
    __shared__ float ssum[4], ssq[4];
    int w = tid >> 5;
    if ((tid & 31) == 0) { ssum[w] = s; ssq[w] = sq; }
    __syncthreads();
    s  = ssum[0] + ssum[1] + ssum[2] + ssum[3];
    sq = ssq[0] + ssq[1] + ssq[2] + ssq[3];
    float mean = s * (1.f / 512.f);
    float var  = sq * (1.f / 512.f) - mean * mean;
    float rstd = rsqrtf(var + 1e-5f);
    float4 gv = *(const float4*)(g + tid * 4);
    float4 bv = *(const float4*)(b + tid * 4);
    float4 o;
    o.x = (v0 - mean) * rstd * gv.x + bv.x;
    o.y = (v1 - mean) * rstd * gv.y + bv.y;
    o.z = (v2 - mean) * rstd * gv.z + bv.z;
    o.w = (v3 - mean) * rstd * gv.w + bv.w;
    *(float4*)(out + (size_t)row * Dc + tid * 4) = o;
}

// ---------------- launcher ---------------------------------------------------
extern "C" void kernel_launch(void* const* d_in, const int* in_sizes, int n_in,
                              void* d_out, int out_size)
{
    (void)in_sizes; (void)n_in; (void)out_size;
    const float* q_embed  = (const float*)d_in[0];
    const float* qa_embed = (const float*)d_in[1];
    const float* forget   = (const float*)d_in[2];
    const float* pos      = (const float*)d_in[3];
    const float* Wk = (const float*)d_in[4];
    const float* bk = (const float*)d_in[5];
    const float* Wv = (const float*)d_in[6];
    const float* bv = (const float*)d_in[7];
    const float* Wo = (const float*)d_in[8];
    const float* bo = (const float*)d_in[9];
    const float* W1 = (const float*)d_in[10];
    const float* b1 = (const float*)d_in[11];
    const float* W2 = (const float*)d_in[12];
    const float* b2 = (const float*)d_in[13];
    const float* g1  = (const float*)d_in[14];
    const float* be1 = (const float*)d_in[15];
    const float* g2  = (const float*)d_in[16];
    const float* be2 = (const float*)d_in[17];
    float* out = (float*)d_out;

    float *px, *py, *pqk, *pv, *pctx, *pt;
    cudaGetSymbolAddress((void**)&px,   g_x);
    cudaGetSymbolAddress((void**)&py,   g_y);
    cudaGetSymbolAddress((void**)&pqk,  g_qk);
    cudaGetSymbolAddress((void**)&pv,   g_v);
    cudaGetSymbolAddress((void**)&pctx, g_ctx);
    cudaGetSymbolAddress((void**)&pt,   g_t);

    cudaFuncSetAttribute(attn_kernel,
                         cudaFuncAttributeMaxDynamicSharedMemorySize, ATTN_SMEM);

    const int n4 = M * Dc / 4, sd4 = Sc * Dc / 4;
    add_pos_kernel<<<(n4 + 255) / 256, 256>>>(q_embed,  pos, px, n4, sd4);
    add_pos_kernel<<<(n4 + 255) / 256, 256>>>(qa_embed, pos, py, n4, sd4);

    const dim3 gD(Dc / 64, M / 128);     // N=512 GEMMs
    const dim3 gF(FFc / 64, M / 128);    // N=2048 GEMM

    for (int l = 0; l < Lc; l++) {
        gemm_kernel<false><<<gD, 256>>>(px, Wk + (size_t)l * Dc * Dc,  bk + l * Dc,  pqk, Dc, Dc);
        gemm_kernel<false><<<gD, 256>>>(py, Wv + (size_t)l * Dc * Dc,  bv + l * Dc,  pv,  Dc, Dc);
        attn_kernel<<<dim3(Sc / 64, Bc * Hc), 256, ATTN_SMEM>>>(pqk, pv, forget, pctx);
        gemm_kernel<false><<<gD, 256>>>(pctx, Wo + (size_t)l * Dc * Dc, bo + l * Dc, pt,  Dc, Dc);
        resid_ln_kernel<<<M, 128>>>(px, pt, g1 + l * Dc, be1 + l * Dc, px);
        gemm_kernel<true ><<<gF, 256>>>(px, W1 + (size_t)l * Dc * FFc, b1 + l * FFc, pt,  FFc, Dc);
        gemm_kernel<false><<<gD, 256>>>(pt, W2 + (size_t)l * FFc * Dc, b2 + l * Dc,  pctx, Dc, FFc);
        resid_ln_kernel<<<M, 128>>>(px, pctx, g2 + l * Dc, be2 + l * Dc,
                                    (l == Lc - 1) ? out : px);
    }
}

// round 6
// speedup vs baseline: 1.8145x; 1.8145x over previous
#include <cuda_runtime.h>
#include <math.h>
#include <cstdint>

// Problem constants
constexpr int Bc = 32, Sc = 512, Dc = 512, Hc = 8, Lc = 4, FFc = 2048;
constexpr int M = Bc * Sc;          // 16384 token rows
constexpr float SCALE = 0.125f;     // 1/sqrt(64)

// ---------------- scratch (static device memory; no allocations) -------------
__device__ float g_x  [(size_t)M * Dc];
__device__ float g_y  [(size_t)M * Dc];
__device__ float g_qk [(size_t)M * Dc];
__device__ float g_v  [(size_t)M * Dc];
__device__ float g_ctx[(size_t)M * Dc];
__device__ float g_t  [(size_t)M * FFc];
// transposed weights ([N,K] row-major == B col-major for mma .col operand)
__device__ float g_wkT[(size_t)Lc * Dc * Dc];
__device__ float g_wvT[(size_t)Lc * Dc * Dc];
__device__ float g_woT[(size_t)Lc * Dc * Dc];
__device__ float g_w1T[(size_t)Lc * FFc * Dc];
__device__ float g_w2T[(size_t)Lc * Dc * FFc];

// ====================== helpers ==============================================
__device__ __forceinline__ uint32_t smem_u32(const void* p) {
    uint32_t a;
    asm("{ .reg .u64 t; cvta.to.shared.u64 t, %1; cvt.u32.u64 %0, t; }"
        : "=r"(a) : "l"(p));
    return a;
}
__device__ __forceinline__ void cp_async16(uint32_t dst, const void* src) {
    asm volatile("cp.async.cg.shared.global [%0], [%1], 16;"
                 :: "r"(dst), "l"(src) : "memory");
}
__device__ __forceinline__ uint32_t f2tf32(float f) {
    uint32_t r;
    asm("cvt.rna.tf32.f32 %0, %1;" : "=r"(r) : "f"(f));
    return r;
}
__device__ __forceinline__ void mma_tf32_16x8x8(float* c, const uint32_t* a,
                                                const uint32_t* b) {
    asm volatile(
        "mma.sync.aligned.m16n8k8.row.col.f32.tf32.tf32.f32 "
        "{%0,%1,%2,%3}, {%4,%5,%6,%7}, {%8,%9}, {%0,%1,%2,%3};"
        : "+f"(c[0]), "+f"(c[1]), "+f"(c[2]), "+f"(c[3])
        : "r"(a[0]), "r"(a[1]), "r"(a[2]), "r"(a[3]), "r"(b[0]), "r"(b[1]));
}

// ---------------- x = in + pos (pos broadcast over batch) --------------------
__global__ void add_pos_kernel(const float* __restrict__ in,
                               const float* __restrict__ pos,
                               float* __restrict__ out, int n4, int sd4)
{
    int i = blockIdx.x * blockDim.x + threadIdx.x;
    if (i < n4) {
        float4 a = ((const float4*)in)[i];
        float4 p = ((const float4*)pos)[i % sd4];
        a.x += p.x; a.y += p.y; a.z += p.z; a.w += p.w;
        ((float4*)out)[i] = a;
    }
}

// ---------------- batched transpose: out[z][c][r] = in[z][r][c] --------------
__global__ void transpose_batched(const float* __restrict__ in,
                                  float* __restrict__ out, int R, int C)
{
    __shared__ float t[32][33];
    const size_t base = (size_t)blockIdx.z * R * C;
    int c0 = blockIdx.x * 32, r0 = blockIdx.y * 32;
    int tx = threadIdx.x, ty = threadIdx.y;
#pragma unroll
    for (int i = 0; i < 32; i += 8)
        t[ty + i][tx] = in[base + (size_t)(r0 + ty + i) * C + c0 + tx];
    __syncthreads();
#pragma unroll
    for (int i = 0; i < 32; i += 8)
        out[base + (size_t)(c0 + ty + i) * R + r0 + tx] = t[tx][ty + i];
}

// ---------------- tf32 mma.sync GEMM -----------------------------------------
// C[M,N] = A[M,K] @ Bt[N,K]^T + bias (opt ReLU).
// CTA tile 128x128, BK=32, 256 threads (8 warps, 2x4 grid, 64x32 warp tile).
// smem row stride 36 floats -> conflict-free fragment loads.
constexpr int GSTRIDE = 36;                          // floats per smem row
constexpr int GSSZ    = 128 * GSTRIDE;               // floats per operand stage
constexpr int GEMM_SMEM = 2 * 2 * GSSZ * 4;          // 2 stages x (A,B) = 73728 B

template<bool RELU>
__global__ __launch_bounds__(256)
void gemm_mma(const float* __restrict__ A, const float* __restrict__ Bt,
              const float* __restrict__ bias, float* __restrict__ C,
              int N, int K)
{
    extern __shared__ float sm[];
    const int tid = threadIdx.x;
    const int wid = tid >> 5, lane = tid & 31;
    const int wm = wid >> 2, wn = wid & 3;           // warp grid 2x4
    const int lr = lane >> 2, lc = lane & 3;
    const int bm = blockIdx.y * 128, bn = blockIdx.x * 128;
    const int nch = K >> 5;
    const uint32_t sbase = smem_u32(sm);

    float acc[4][4][4];
#pragma unroll
    for (int mi = 0; mi < 4; mi++)
#pragma unroll
        for (int ni = 0; ni < 4; ni++)
#pragma unroll
            for (int q = 0; q < 4; q++) acc[mi][ni][q] = 0.f;

    auto load_stage = [&](int c, int s) {
        const float* Ap = A  + (size_t)bm * K + c * 32;
        const float* Bp = Bt + (size_t)bn * K + c * 32;
        uint32_t dA = sbase + (uint32_t)(s * 2 * GSSZ) * 4;
        uint32_t dB = dA + (uint32_t)GSSZ * 4;
#pragma unroll
        for (int q = 0; q < 4; q++) {
            int idx = q * 256 + tid;
            int row = idx >> 3, c4 = idx & 7;
            uint32_t off = (uint32_t)(row * GSTRIDE + c4 * 4) * 4;
            cp_async16(dA + off, Ap + (size_t)row * K + c4 * 4);
            cp_async16(dB + off, Bp + (size_t)row * K + c4 * 4);
        }
        asm volatile("cp.async.commit_group;" ::: "memory");
    };

    load_stage(0, 0);
    for (int c = 0; c < nch; ++c) {
        const int s = c & 1;
        if (c + 1 < nch) {
            load_stage(c + 1, s ^ 1);
            asm volatile("cp.async.wait_group 1;" ::: "memory");
        } else {
            asm volatile("cp.async.wait_group 0;" ::: "memory");
        }
        __syncthreads();

        const float* cA = sm + s * 2 * GSSZ;
        const float* cB = cA + GSSZ;
#pragma unroll
        for (int kk = 0; kk < 4; kk++) {
            uint32_t af[4][4], bf[4][2];
#pragma unroll
            for (int mi = 0; mi < 4; mi++) {
                int base = (wm * 64 + mi * 16 + lr) * GSTRIDE + kk * 8 + lc;
                af[mi][0] = f2tf32(cA[base]);
                af[mi][1] = f2tf32(cA[base + 8 * GSTRIDE]);
                af[mi][2] = f2tf32(cA[base + 4]);
                af[mi][3] = f2tf32(cA[base + 8 * GSTRIDE + 4]);
            }
#pragma unroll
            for (int ni = 0; ni < 4; ni++) {
                int base = (wn * 32 + ni * 8 + lr) * GSTRIDE + kk * 8 + lc;
                bf[ni][0] = f2tf32(cB[base]);
                bf[ni][1] = f2tf32(cB[base + 4]);
            }
#pragma unroll
            for (int mi = 0; mi < 4; mi++)
#pragma unroll
                for (int ni = 0; ni < 4; ni++)
                    mma_tf32_16x8x8(acc[mi][ni], af[mi], bf[ni]);
        }
        __syncthreads();
    }

    // epilogue: bias (+ReLU), direct global stores (float2 per fragment half)
#pragma unroll
    for (int mi = 0; mi < 4; mi++) {
        int row0 = bm + wm * 64 + mi * 16 + lr;
#pragma unroll
        for (int ni = 0; ni < 4; ni++) {
            int col = bn + wn * 32 + ni * 8 + 2 * lc;
            float b0 = bias[col], b1 = bias[col + 1];
            float2 o0 = make_float2(acc[mi][ni][0] + b0, acc[mi][ni][1] + b1);
            float2 o1 = make_float2(acc[mi][ni][2] + b0, acc[mi][ni][3] + b1);
            if (RELU) {
                o0.x = fmaxf(o0.x, 0.f); o0.y = fmaxf(o0.y, 0.f);
                o1.x = fmaxf(o1.x, 0.f); o1.y = fmaxf(o1.y, 0.f);
            }
            *(float2*)(C + (size_t)row0 * N + col) = o0;
            *(float2*)(C + (size_t)(row0 + 8) * N + col) = o1;
        }
    }
}

// ---------------- fused attention (flash-style, fp32) ------------------------
constexpr int ATTN_SMEM = (64 * 68 * 2 + 64 * 65 + 64 * 64 + 64) * 4;

__global__ __launch_bounds__(256)
void attn_kernel(const float* __restrict__ qk, const float* __restrict__ v,
                 const float* __restrict__ forget, float* __restrict__ ctx)
{
    extern __shared__ float sm[];
    float* Qs = sm;                  // [64][68]
    float* Ks = Qs + 64 * 68;        // [64][68]
    float* Ss = Ks + 64 * 68;        // [64][65]
    float* Vs = Ss + 64 * 65;        // [64][64]
    float* Fr = Vs + 64 * 64;        // [64]

    const int tid = threadIdx.x;
    const int it = blockIdx.x;
    const int bh = blockIdx.y;
    const int b = bh >> 3, h = bh & 7;
    const int i0 = it * 64;

    const float* Qbase = qk + ((size_t)b * Sc) * Dc + h * 64;
    const float* Vbase = v  + ((size_t)b * Sc) * Dc + h * 64;

#pragma unroll
    for (int q = 0; q < 4; q++) {
        int idx = tid + q * 256;
        int r = idx >> 4, c4 = idx & 15;
        *(float4*)(&Qs[r * 68 + c4 * 4]) =
            *(const float4*)(Qbase + (size_t)(i0 + r) * Dc + c4 * 4);
    }
    if (tid < 64) Fr[tid] = forget[b * Sc + i0 + tid];

    const int tr = tid >> 4, tc = tid & 15;
    const int r  = tid >> 2, cg = tid & 3;
    float mrow = -3.0e30f, lsum = 0.0f;
    float acc[16];
#pragma unroll
    for (int i = 0; i < 16; i++) acc[i] = 0.f;

    for (int jt = 0; jt <= it; jt++) {
        __syncthreads();
#pragma unroll
        for (int q = 0; q < 4; q++) {
            int idx = tid + q * 256;
            int rr = idx >> 4, c4 = idx & 15;
            *(float4*)(&Ks[rr * 68 + c4 * 4]) =
                *(const float4*)(Qbase + (size_t)(jt * 64 + rr) * Dc + c4 * 4);
            *(float4*)(&Vs[rr * 64 + c4 * 4]) =
                *(const float4*)(Vbase + (size_t)(jt * 64 + rr) * Dc + c4 * 4);
        }
        __syncthreads();

        float sacc[4][4];
#pragma unroll
        for (int i = 0; i < 4; i++)
#pragma unroll
            for (int j = 0; j < 4; j++) sacc[i][j] = 0.f;
#pragma unroll
        for (int k = 0; k < 64; k += 4) {
            float4 a[4], bb[4];
#pragma unroll
            for (int i = 0; i < 4; i++) a[i]  = *(float4*)(&Qs[(tr * 4 + i) * 68 + k]);
#pragma unroll
            for (int j = 0; j < 4; j++) bb[j] = *(float4*)(&Ks[(tc * 4 + j) * 68 + k]);
#pragma unroll
            for (int i = 0; i < 4; i++)
#pragma unroll
                for (int j = 0; j < 4; j++)
                    sacc[i][j] += a[i].x * bb[j].x + a[i].y * bb[j].y
                                + a[i].z * bb[j].z + a[i].w * bb[j].w;
        }
#pragma unroll
        for (int i = 0; i < 4; i++) {
            int il = tr * 4 + i;
            float f = SCALE * Fr[il];
#pragma unroll
            for (int j = 0; j < 4; j++) {
                int jl = tc * 4 + j;
                float sval = ((jt * 64 + jl) < (i0 + il)) ? sacc[i][j] * f : -1.0e30f;
                Ss[il * 65 + jl] = sval;
            }
        }
        __syncthreads();

        float tmax = -3.0e30f;
#pragma unroll
        for (int j = 0; j < 64; j++) tmax = fmaxf(tmax, Ss[r * 65 + j]);
        float mnew = fmaxf(mrow, tmax);
        float corr = __expf(mrow - mnew);
        lsum *= corr;
#pragma unroll
        for (int i = 0; i < 16; i++) acc[i] *= corr;
#pragma unroll
        for (int j = 0; j < 64; j++) {
            float p = __expf(Ss[r * 65 + j] - mnew);
            lsum += p;
            const float* vrow = &Vs[j * 64 + cg * 16];
#pragma unroll
            for (int q2 = 0; q2 < 4; q2++) {
                float4 vv = *(const float4*)(vrow + q2 * 4);
                acc[q2 * 4 + 0] += p * vv.x;
                acc[q2 * 4 + 1] += p * vv.y;
                acc[q2 * 4 + 2] += p * vv.z;
                acc[q2 * 4 + 3] += p * vv.w;
            }
        }
        mrow = mnew;
    }

    float inv = (i0 + r == 0) ? 0.0f : 1.0f / lsum;
    float* out = ctx + ((size_t)b * Sc + i0 + r) * Dc + h * 64 + cg * 16;
#pragma unroll
    for (int q2 = 0; q2 < 4; q2++) {
        float4 o = make_float4(acc[q2 * 4 + 0] * inv, acc[q2 * 4 + 1] * inv,
                               acc[q2 * 4 + 2] * inv, acc[q2 * 4 + 3] * inv);
        *(float4*)(out + q2 * 4) = o;
    }
}

// ---------------- fused residual + LayerNorm ---------------------------------
__global__ __launch_bounds__(128)
void resid_ln_kernel(const float* __restrict__ x, const float* __restrict__ t,
                     const float* __restrict__ g, const float* __restrict__ b,
                     float* __restrict__ out)
{
    const int row = blockIdx.x;
    const int tid = threadIdx.x;
    float4 xv = *(const float4*)(x + (size_t)row * Dc + tid * 4);
    float4 tv = *(const float4*)(t + (size_t)row * Dc + tid * 4);
    float v0 = xv.x + tv.x, v1 = xv.y + tv.y, v2 = xv.z + tv.z, v3 = xv.w + tv.w;
    float s  = v0 + v1 + v2 + v3;
    float sq = v0 * v0 + v1 * v1 + v2 * v2 + v3 * v3;
#pragma unroll
    for (int o = 16; o; o >>= 1) {
        s  += __shfl_xor_sync(0xffffffffu, s, o);
        sq += __shfl_xor_sync(0xffffffffu, sq, o);
    }
    __shared__ float ssum[4], ssq[4];
    int w = tid >> 5;
    if ((tid & 31) == 0) { ssum[w] = s; ssq[w] = sq; }
    __syncthreads();
    s  = ssum[0] + ssum[1] + ssum[2] + ssum[3];
    sq = ssq[0] + ssq[1] + ssq[2] + ssq[3];
    float mean = s * (1.f / 512.f);
    float var  = sq * (1.f / 512.f) - mean * mean;
    float rstd = rsqrtf(var + 1e-5f);
    float4 gv = *(const float4*)(g + tid * 4);
    float4 bv = *(const float4*)(b + tid * 4);
    float4 o;
    o.x = (v0 - mean) * rstd * gv.x + bv.x;
    o.y = (v1 - mean) * rstd * gv.y + bv.y;
    o.z = (v2 - mean) * rstd * gv.z + bv.z;
    o.w = (v3 - mean) * rstd * gv.w + bv.w;
    *(float4*)(out + (size_t)row * Dc + tid * 4) = o;
}

// ---------------- launcher ---------------------------------------------------
extern "C" void kernel_launch(void* const* d_in, const int* in_sizes, int n_in,
                              void* d_out, int out_size)
{
    (void)in_sizes; (void)n_in; (void)out_size;
    const float* q_embed  = (const float*)d_in[0];
    const float* qa_embed = (const float*)d_in[1];
    const float* forget   = (const float*)d_in[2];
    const float* pos      = (const float*)d_in[3];
    const float* Wk = (const float*)d_in[4];
    const float* bk = (const float*)d_in[5];
    const float* Wv = (const float*)d_in[6];
    const float* bv = (const float*)d_in[7];
    const float* Wo = (const float*)d_in[8];
    const float* bo = (const float*)d_in[9];
    const float* W1 = (const float*)d_in[10];
    const float* b1 = (const float*)d_in[11];
    const float* W2 = (const float*)d_in[12];
    const float* b2 = (const float*)d_in[13];
    const float* g1  = (const float*)d_in[14];
    const float* be1 = (const float*)d_in[15];
    const float* g2  = (const float*)d_in[16];
    const float* be2 = (const float*)d_in[17];
    float* out = (float*)d_out;

    float *px, *py, *pqk, *pv, *pctx, *pt;
    float *pwkT, *pwvT, *pwoT, *pw1T, *pw2T;
    cudaGetSymbolAddress((void**)&px,   g_x);
    cudaGetSymbolAddress((void**)&py,   g_y);
    cudaGetSymbolAddress((void**)&pqk,  g_qk);
    cudaGetSymbolAddress((void**)&pv,   g_v);
    cudaGetSymbolAddress((void**)&pctx, g_ctx);
    cudaGetSymbolAddress((void**)&pt,   g_t);
    cudaGetSymbolAddress((void**)&pwkT, g_wkT);
    cudaGetSymbolAddress((void**)&pwvT, g_wvT);
    cudaGetSymbolAddress((void**)&pwoT, g_woT);
    cudaGetSymbolAddress((void**)&pw1T, g_w1T);
    cudaGetSymbolAddress((void**)&pw2T, g_w2T);

    cudaFuncSetAttribute(attn_kernel,
                         cudaFuncAttributeMaxDynamicSharedMemorySize, ATTN_SMEM);
    cudaFuncSetAttribute(gemm_mma<false>,
                         cudaFuncAttributeMaxDynamicSharedMemorySize, GEMM_SMEM);
    cudaFuncSetAttribute(gemm_mma<true>,
                         cudaFuncAttributeMaxDynamicSharedMemorySize, GEMM_SMEM);

    // weight transposes -> [N,K] (B col-major for mma .col operand)
    const dim3 tb(32, 8);
    transpose_batched<<<dim3(Dc / 32, Dc / 32, Lc), tb>>>(Wk, pwkT, Dc, Dc);
    transpose_batched<<<dim3(Dc / 32, Dc / 32, Lc), tb>>>(Wv, pwvT, Dc, Dc);
    transpose_batched<<<dim3(Dc / 32, Dc / 32, Lc), tb>>>(Wo, pwoT, Dc, Dc);
    transpose_batched<<<dim3(FFc / 32, Dc / 32, Lc), tb>>>(W1, pw1T, Dc, FFc);
    transpose_batched<<<dim3(Dc / 32, FFc / 32, Lc), tb>>>(W2, pw2T, FFc, Dc);

    const int n4 = M * Dc / 4, sd4 = Sc * Dc / 4;
    add_pos_kernel<<<(n4 + 255) / 256, 256>>>(q_embed,  pos, px, n4, sd4);
    add_pos_kernel<<<(n4 + 255) / 256, 256>>>(qa_embed, pos, py, n4, sd4);

    const dim3 gD(Dc / 128, M / 128);     // N=512 GEMMs
    const dim3 gF(FFc / 128, M / 128);    // N=2048 GEMM

    for (int l = 0; l < Lc; l++) {
        gemm_mma<false><<<gD, 256, GEMM_SMEM>>>(px,  pwkT + (size_t)l * Dc * Dc,  bk + l * Dc,  pqk, Dc, Dc);
        gemm_mma<false><<<gD, 256, GEMM_SMEM>>>(py,  pwvT + (size_t)l * Dc * Dc,  bv + l * Dc,  pv,  Dc, Dc);
        attn_kernel<<<dim3(Sc / 64, Bc * Hc), 256, ATTN_SMEM>>>(pqk, pv, forget, pctx);
        gemm_mma<false><<<gD, 256, GEMM_SMEM>>>(pctx, pwoT + (size_t)l * Dc * Dc, bo + l * Dc, pt,  Dc, Dc);
        resid_ln_kernel<<<M, 128>>>(px, pt, g1 + l * Dc, be1 + l * Dc, px);
        gemm_mma<true ><<<gF, 256, GEMM_SMEM>>>(px, pw1T + (size_t)l * FFc * Dc, b1 + l * FFc, pt,  FFc, Dc);
        gemm_mma<false><<<gD, 256, GEMM_SMEM>>>(pt, pw2T + (size_t)l * Dc * FFc, b2 + l * Dc,  pctx, Dc, FFc);
        resid_ln_kernel<<<M, 128>>>(px, pctx, g2 + l * Dc, be2 + l * Dc,
                                    (l == Lc - 1) ? out : px);
    }
}

// round 7
// speedup vs baseline: 3.3138x; 1.8263x over previous
#include <cuda_runtime.h>
#include <math.h>
#include <cstdint>

// Problem constants
constexpr int Bc = 32, Sc = 512, Dc = 512, Hc = 8, Lc = 4, FFc = 2048;
constexpr int M = Bc * Sc;          // 16384 token rows
constexpr float SCALE = 0.125f;     // 1/sqrt(64)

// ---------------- scratch (static device memory; no allocations) -------------
__device__ float g_x  [(size_t)M * Dc];
__device__ float g_y  [(size_t)M * Dc];
__device__ float g_qk [(size_t)M * Dc];
__device__ float g_v  [(size_t)M * Dc];
__device__ float g_ctx[(size_t)M * Dc];
__device__ float g_t  [(size_t)M * FFc];
// transposed weights ([N,K] row-major == B col-major for mma .col operand)
__device__ float g_wkT[(size_t)Lc * Dc * Dc];
__device__ float g_wvT[(size_t)Lc * Dc * Dc];
__device__ float g_woT[(size_t)Lc * Dc * Dc];
__device__ float g_w1T[(size_t)Lc * FFc * Dc];
__device__ float g_w2T[(size_t)Lc * Dc * FFc];

// ====================== helpers ==============================================
__device__ __forceinline__ uint32_t smem_u32(const void* p) {
    uint32_t a;
    asm("{ .reg .u64 t; cvta.to.shared.u64 t, %1; cvt.u32.u64 %0, t; }"
        : "=r"(a) : "l"(p));
    return a;
}
__device__ __forceinline__ void cp_async16(uint32_t dst, const void* src) {
    asm volatile("cp.async.cg.shared.global [%0], [%1], 16;"
                 :: "r"(dst), "l"(src) : "memory");
}
__device__ __forceinline__ uint32_t f2tf32(float f) {
    uint32_t r;
    asm("cvt.rna.tf32.f32 %0, %1;" : "=r"(r) : "f"(f));
    return r;
}
__device__ __forceinline__ void mma_tf32_16x8x8(float* c, const uint32_t* a,
                                                const uint32_t* b) {
    asm volatile(
        "mma.sync.aligned.m16n8k8.row.col.f32.tf32.tf32.f32 "
        "{%0,%1,%2,%3}, {%4,%5,%6,%7}, {%8,%9}, {%0,%1,%2,%3};"
        : "+f"(c[0]), "+f"(c[1]), "+f"(c[2]), "+f"(c[3])
        : "r"(a[0]), "r"(a[1]), "r"(a[2]), "r"(a[3]), "r"(b[0]), "r"(b[1]));
}

// ---------------- x = in + pos (pos broadcast over batch) --------------------
__global__ void add_pos_kernel(const float* __restrict__ in,
                               const float* __restrict__ pos,
                               float* __restrict__ out, int n4, int sd4)
{
    int i = blockIdx.x * blockDim.x + threadIdx.x;
    if (i < n4) {
        float4 a = ((const float4*)in)[i];
        float4 p = ((const float4*)pos)[i % sd4];
        a.x += p.x; a.y += p.y; a.z += p.z; a.w += p.w;
        ((float4*)out)[i] = a;
    }
}

// ---------------- batched transpose: out[z][c][r] = in[z][r][c] --------------
__global__ void transpose_batched(const float* __restrict__ in,
                                  float* __restrict__ out, int R, int C)
{
    __shared__ float t[32][33];
    const size_t base = (size_t)blockIdx.z * R * C;
    int c0 = blockIdx.x * 32, r0 = blockIdx.y * 32;
    int tx = threadIdx.x, ty = threadIdx.y;
#pragma unroll
    for (int i = 0; i < 32; i += 8)
        t[ty + i][tx] = in[base + (size_t)(r0 + ty + i) * C + c0 + tx];
    __syncthreads();
#pragma unroll
    for (int i = 0; i < 32; i += 8)
        out[base + (size_t)(c0 + ty + i) * R + r0 + tx] = t[tx][ty + i];
}

// ---------------- tf32 mma.sync GEMM -----------------------------------------
constexpr int GSTRIDE = 36;                          // floats per smem row
constexpr int GSSZ    = 128 * GSTRIDE;               // floats per operand stage
constexpr int GEMM_SMEM = 2 * 2 * GSSZ * 4;          // 2 stages x (A,B) = 73728 B

template<bool RELU>
__global__ __launch_bounds__(256)
void gemm_mma(const float* __restrict__ A, const float* __restrict__ Bt,
              const float* __restrict__ bias, float* __restrict__ C,
              int N, int K)
{
    extern __shared__ float sm[];
    const int tid = threadIdx.x;
    const int wid = tid >> 5, lane = tid & 31;
    const int wm = wid >> 2, wn = wid & 3;           // warp grid 2x4
    const int lr = lane >> 2, lc = lane & 3;
    const int bm = blockIdx.y * 128, bn = blockIdx.x * 128;
    const int nch = K >> 5;
    const uint32_t sbase = smem_u32(sm);

    float acc[4][4][4];
#pragma unroll
    for (int mi = 0; mi < 4; mi++)
#pragma unroll
        for (int ni = 0; ni < 4; ni++)
#pragma unroll
            for (int q = 0; q < 4; q++) acc[mi][ni][q] = 0.f;

    auto load_stage = [&](int c, int s) {
        const float* Ap = A  + (size_t)bm * K + c * 32;
        const float* Bp = Bt + (size_t)bn * K + c * 32;
        uint32_t dA = sbase + (uint32_t)(s * 2 * GSSZ) * 4;
        uint32_t dB = dA + (uint32_t)GSSZ * 4;
#pragma unroll
        for (int q = 0; q < 4; q++) {
            int idx = q * 256 + tid;
            int row = idx >> 3, c4 = idx & 7;
            uint32_t off = (uint32_t)(row * GSTRIDE + c4 * 4) * 4;
            cp_async16(dA + off, Ap + (size_t)row * K + c4 * 4);
            cp_async16(dB + off, Bp + (size_t)row * K + c4 * 4);
        }
        asm volatile("cp.async.commit_group;" ::: "memory");
    };

    load_stage(0, 0);
    for (int c = 0; c < nch; ++c) {
        const int s = c & 1;
        if (c + 1 < nch) {
            load_stage(c + 1, s ^ 1);
            asm volatile("cp.async.wait_group 1;" ::: "memory");
        } else {
            asm volatile("cp.async.wait_group 0;" ::: "memory");
        }
        __syncthreads();

        const float* cA = sm + s * 2 * GSSZ;
        const float* cB = cA + GSSZ;
#pragma unroll
        for (int kk = 0; kk < 4; kk++) {
            uint32_t af[4][4], bf[4][2];
#pragma unroll
            for (int mi = 0; mi < 4; mi++) {
                int base = (wm * 64 + mi * 16 + lr) * GSTRIDE + kk * 8 + lc;
                af[mi][0] = f2tf32(cA[base]);
                af[mi][1] = f2tf32(cA[base + 8 * GSTRIDE]);
                af[mi][2] = f2tf32(cA[base + 4]);
                af[mi][3] = f2tf32(cA[base + 8 * GSTRIDE + 4]);
            }
#pragma unroll
            for (int ni = 0; ni < 4; ni++) {
                int base = (wn * 32 + ni * 8 + lr) * GSTRIDE + kk * 8 + lc;
                bf[ni][0] = f2tf32(cB[base]);
                bf[ni][1] = f2tf32(cB[base + 4]);
            }
#pragma unroll
            for (int mi = 0; mi < 4; mi++)
#pragma unroll
                for (int ni = 0; ni < 4; ni++)
                    mma_tf32_16x8x8(acc[mi][ni], af[mi], bf[ni]);
        }
        __syncthreads();
    }

#pragma unroll
    for (int mi = 0; mi < 4; mi++) {
        int row0 = bm + wm * 64 + mi * 16 + lr;
#pragma unroll
        for (int ni = 0; ni < 4; ni++) {
            int col = bn + wn * 32 + ni * 8 + 2 * lc;
            float b0 = bias[col], b1 = bias[col + 1];
            float2 o0 = make_float2(acc[mi][ni][0] + b0, acc[mi][ni][1] + b1);
            float2 o1 = make_float2(acc[mi][ni][2] + b0, acc[mi][ni][3] + b1);
            if (RELU) {
                o0.x = fmaxf(o0.x, 0.f); o0.y = fmaxf(o0.y, 0.f);
                o1.x = fmaxf(o1.x, 0.f); o1.y = fmaxf(o1.y, 0.f);
            }
            *(float2*)(C + (size_t)row0 * N + col) = o0;
            *(float2*)(C + (size_t)(row0 + 8) * N + col) = o1;
        }
    }
}

// ---------------- tensor-core fused attention --------------------------------
// CTA per (b, h, 64-row i-tile), 256 threads (8 warps, 4x2 grid, warp tile
// 16x32). S = Q K^T and O += P V via m16n8k8 tf32 mma; softmax scalar fp32.
constexpr int AST = 68;   // smem row stride (68 % 32 == 4 -> conflict-free frags)
constexpr int ATTN_SMEM = (4 * 64 * AST + 192) * 4;

__global__ __launch_bounds__(256)
void attn_mma(const float* __restrict__ qk, const float* __restrict__ v,
              const float* __restrict__ forget, float* __restrict__ ctx)
{
    extern __shared__ float sm[];
    float* Qs = sm;                    // [64][AST]
    float* Ks = Qs + 64 * AST;         // [64][AST]
    float* Vt = Ks + 64 * AST;         // [64 d][AST] (V transposed)
    float* Ss = Vt + 64 * AST;         // [64][AST]  scores -> P in-place
    float* Fr = Ss + 64 * AST;         // [64]
    float* Cr = Fr + 64;               // [64] per-row corr
    float* Li = Cr + 64;               // [64] per-row 1/lsum

    const int tid = threadIdx.x;
    const int wid = tid >> 5, lane = tid & 31;
    const int lr = lane >> 2, lc = lane & 3;
    const int wm = wid & 3, wn2 = wid >> 2;        // 4x2 warp grid
    const int it = blockIdx.x, bh = blockIdx.y;
    const int b = bh >> 3, h = bh & 7;
    const int i0 = it * 64;

    const float* Qbase = qk + ((size_t)b * Sc) * Dc + h * 64;
    const float* Vbase = v  + ((size_t)b * Sc) * Dc + h * 64;

    // Q tile (once)
#pragma unroll
    for (int q = 0; q < 4; q++) {
        int idx = tid + q * 256;
        int r = idx >> 4, c4 = idx & 15;
        *(float4*)(&Qs[r * AST + c4 * 4]) =
            *(const float4*)(Qbase + (size_t)(i0 + r) * Dc + c4 * 4);
    }
    if (tid < 64) Fr[tid] = forget[b * Sc + i0 + tid];

    const int il0 = wm * 16 + lr, il1 = il0 + 8;   // fragment rows
    const int sr = tid >> 2, scg = tid & 3;        // softmax mapping

    float mrow = -3.0e30f, lsum = 0.0f;
    float oacc[4][4];
#pragma unroll
    for (int ni = 0; ni < 4; ni++)
#pragma unroll
        for (int q = 0; q < 4; q++) oacc[ni][q] = 0.f;

    const int vc4 = tid >> 4, vrl = tid & 15;      // Vt store mapping

    for (int jt = 0; jt <= it; jt++) {
        __syncthreads();   // prior PV reads of Ks/Vt/Ss done
        // K tile: coalesced float4 rows
#pragma unroll
        for (int q = 0; q < 4; q++) {
            int idx = tid + q * 256;
            int rr = idx >> 4, c4 = idx & 15;
            *(float4*)(&Ks[rr * AST + c4 * 4]) =
                *(const float4*)(Qbase + (size_t)(jt * 64 + rr) * Dc + c4 * 4);
        }
        // V transposed into Vt[d][j] (conflict-free scalar stores)
#pragma unroll
        for (int q2 = 0; q2 < 4; q2++) {
            int row = q2 * 16 + vrl;
            float4 vv = *(const float4*)(Vbase + (size_t)(jt * 64 + row) * Dc + vc4 * 4);
            Vt[(vc4 * 4 + 0) * AST + row] = vv.x;
            Vt[(vc4 * 4 + 1) * AST + row] = vv.y;
            Vt[(vc4 * 4 + 2) * AST + row] = vv.z;
            Vt[(vc4 * 4 + 3) * AST + row] = vv.w;
        }
        __syncthreads();

        // ---- S = Q K^T (warp tile 16x32) ----
        float sfr[4][4];
#pragma unroll
        for (int ni = 0; ni < 4; ni++)
#pragma unroll
            for (int q = 0; q < 4; q++) sfr[ni][q] = 0.f;
#pragma unroll
        for (int kk = 0; kk < 8; kk++) {
            uint32_t af[4];
            int ab = il0 * AST + kk * 8 + lc;
            af[0] = f2tf32(Qs[ab]);
            af[1] = f2tf32(Qs[ab + 8 * AST]);
            af[2] = f2tf32(Qs[ab + 4]);
            af[3] = f2tf32(Qs[ab + 8 * AST + 4]);
#pragma unroll
            for (int ni = 0; ni < 4; ni++) {
                int bb = (wn2 * 32 + ni * 8 + lr) * AST + kk * 8 + lc;
                uint32_t bf[2] = { f2tf32(Ks[bb]), f2tf32(Ks[bb + 4]) };
                mma_tf32_16x8x8(sfr[ni], af, bf);
            }
        }
        // masked, forget-scaled write to Ss
        {
            float f0 = SCALE * Fr[il0], f1 = SCALE * Fr[il1];
            int gi0 = i0 + il0, gi1 = i0 + il1;
#pragma unroll
            for (int ni = 0; ni < 4; ni++) {
                int jl = wn2 * 32 + ni * 8 + 2 * lc;
                int gj = jt * 64 + jl;
                float2 s0, s1;
                s0.x = (gj     < gi0) ? sfr[ni][0] * f0 : -1.0e30f;
                s0.y = (gj + 1 < gi0) ? sfr[ni][1] * f0 : -1.0e30f;
                s1.x = (gj     < gi1) ? sfr[ni][2] * f1 : -1.0e30f;
                s1.y = (gj + 1 < gi1) ? sfr[ni][3] * f1 : -1.0e30f;
                *(float2*)(&Ss[il0 * AST + jl]) = s0;
                *(float2*)(&Ss[il1 * AST + jl]) = s1;
            }
        }
        __syncthreads();

        // ---- online softmax: thread owns (row sr, cols scg*16..+16) ----
        {
            float p[16];
            const int base = sr * AST + scg * 16;
            float tmax = -3.0e30f;
#pragma unroll
            for (int j = 0; j < 16; j++) { p[j] = Ss[base + j]; tmax = fmaxf(tmax, p[j]); }
            tmax = fmaxf(tmax, __shfl_xor_sync(0xffffffffu, tmax, 1));
            tmax = fmaxf(tmax, __shfl_xor_sync(0xffffffffu, tmax, 2));
            float mnew = fmaxf(mrow, tmax);
            float cor = __expf(mrow - mnew);
            float ls = 0.f;
#pragma unroll
            for (int j = 0; j < 16; j++) {
                p[j] = __expf(p[j] - mnew);
                ls += p[j];
                Ss[base + j] = p[j];
            }
            ls += __shfl_xor_sync(0xffffffffu, ls, 1);
            ls += __shfl_xor_sync(0xffffffffu, ls, 2);
            lsum = lsum * cor + ls;
            mrow = mnew;
            if (scg == 0) Cr[sr] = cor;
        }
        __syncthreads();

        // ---- O = O*corr + P V ----
        {
            float c0 = Cr[il0], c1 = Cr[il1];
#pragma unroll
            for (int ni = 0; ni < 4; ni++) {
                oacc[ni][0] *= c0; oacc[ni][1] *= c0;
                oacc[ni][2] *= c1; oacc[ni][3] *= c1;
            }
#pragma unroll
            for (int kk = 0; kk < 8; kk++) {
                uint32_t af[4];
                int ab = il0 * AST + kk * 8 + lc;
                af[0] = f2tf32(Ss[ab]);
                af[1] = f2tf32(Ss[ab + 8 * AST]);
                af[2] = f2tf32(Ss[ab + 4]);
                af[3] = f2tf32(Ss[ab + 8 * AST + 4]);
#pragma unroll
                for (int ni = 0; ni < 4; ni++) {
                    int bb = (wn2 * 32 + ni * 8 + lr) * AST + kk * 8 + lc;
                    uint32_t bf[2] = { f2tf32(Vt[bb]), f2tf32(Vt[bb + 4]) };
                    mma_tf32_16x8x8(oacc[ni], af, bf);
                }
            }
        }
    }

    // epilogue: normalize (row 0 of each sequence zeroed)
    if (scg == 0) Li[sr] = (i0 + sr == 0) ? 0.f : 1.f / lsum;
    __syncthreads();
    {
        float l0 = Li[il0], l1 = Li[il1];
        float* ob = ctx + ((size_t)b * Sc + i0) * Dc + h * 64;
#pragma unroll
        for (int ni = 0; ni < 4; ni++) {
            int col = wn2 * 32 + ni * 8 + 2 * lc;
            float2 o0 = make_float2(oacc[ni][0] * l0, oacc[ni][1] * l0);
            float2 o1 = make_float2(oacc[ni][2] * l1, oacc[ni][3] * l1);
            *(float2*)(ob + (size_t)il0 * Dc + col) = o0;
            *(float2*)(ob + (size_t)il1 * Dc + col) = o1;
        }
    }
}

// ---------------- fused residual + LayerNorm ---------------------------------
__global__ __launch_bounds__(128)
void resid_ln_kernel(const float* __restrict__ x, const float* __restrict__ t,
                     const float* __restrict__ g, const float* __restrict__ b,
                     float* __restrict__ out)
{
    const int row = blockIdx.x;
    const int tid = threadIdx.x;
    float4 xv = *(const float4*)(x + (size_t)row * Dc + tid * 4);
    float4 tv = *(const float4*)(t + (size_t)row * Dc + tid * 4);
    float v0 = xv.x + tv.x, v1 = xv.y + tv.y, v2 = xv.z + tv.z, v3 = xv.w + tv.w;
    float s  = v0 + v1 + v2 + v3;
    float sq = v0 * v0 + v1 * v1 + v2 * v2 + v3 * v3;
#pragma unroll
    for (int o = 16; o; o >>= 1) {
        s  += __shfl_xor_sync(0xffffffffu, s, o);
        sq += __shfl_xor_sync(0xffffffffu, sq, o);
    }
    __shared__ float ssum[4], ssq[4];
    int w = tid >> 5;
    if ((tid & 31) == 0) { ssum[w] = s; ssq[w] = sq; }
    __syncthreads();
    s  = ssum[0] + ssum[1] + ssum[2] + ssum[3];
    sq = ssq[0] + ssq[1] + ssq[2] + ssq[3];
    float mean = s * (1.f / 512.f);
    float var  = sq * (1.f / 512.f) - mean * mean;
    float rstd = rsqrtf(var + 1e-5f);
    float4 gv = *(const float4*)(g + tid * 4);
    float4 bv = *(const float4*)(b + tid * 4);
    float4 o;
    o.x = (v0 - mean) * rstd * gv.x + bv.x;
    o.y = (v1 - mean) * rstd * gv.y + bv.y;
    o.z = (v2 - mean) * rstd * gv.z + bv.z;
    o.w = (v3 - mean) * rstd * gv.w + bv.w;
    *(float4*)(out + (size_t)row * Dc + tid * 4) = o;
}

// ---------------- launcher ---------------------------------------------------
extern "C" void kernel_launch(void* const* d_in, const int* in_sizes, int n_in,
                              void* d_out, int out_size)
{
    (void)in_sizes; (void)n_in; (void)out_size;
    const float* q_embed  = (const float*)d_in[0];
    const float* qa_embed = (const float*)d_in[1];
    const float* forget   = (const float*)d_in[2];
    const float* pos      = (const float*)d_in[3];
    const float* Wk = (const float*)d_in[4];
    const float* bk = (const float*)d_in[5];
    const float* Wv = (const float*)d_in[6];
    const float* bv = (const float*)d_in[7];
    const float* Wo = (const float*)d_in[8];
    const float* bo = (const float*)d_in[9];
    const float* W1 = (const float*)d_in[10];
    const float* b1 = (const float*)d_in[11];
    const float* W2 = (const float*)d_in[12];
    const float* b2 = (const float*)d_in[13];
    const float* g1  = (const float*)d_in[14];
    const float* be1 = (const float*)d_in[15];
    const float* g2  = (const float*)d_in[16];
    const float* be2 = (const float*)d_in[17];
    float* out = (float*)d_out;

    float *px, *py, *pqk, *pv, *pctx, *pt;
    float *pwkT, *pwvT, *pwoT, *pw1T, *pw2T;
    cudaGetSymbolAddress((void**)&px,   g_x);
    cudaGetSymbolAddress((void**)&py,   g_y);
    cudaGetSymbolAddress((void**)&pqk,  g_qk);
    cudaGetSymbolAddress((void**)&pv,   g_v);
    cudaGetSymbolAddress((void**)&pctx, g_ctx);
    cudaGetSymbolAddress((void**)&pt,   g_t);
    cudaGetSymbolAddress((void**)&pwkT, g_wkT);
    cudaGetSymbolAddress((void**)&pwvT, g_wvT);
    cudaGetSymbolAddress((void**)&pwoT, g_woT);
    cudaGetSymbolAddress((void**)&pw1T, g_w1T);
    cudaGetSymbolAddress((void**)&pw2T, g_w2T);

    cudaFuncSetAttribute(attn_mma,
                         cudaFuncAttributeMaxDynamicSharedMemorySize, ATTN_SMEM);
    cudaFuncSetAttribute(gemm_mma<false>,
                         cudaFuncAttributeMaxDynamicSharedMemorySize, GEMM_SMEM);
    cudaFuncSetAttribute(gemm_mma<true>,
                         cudaFuncAttributeMaxDynamicSharedMemorySize, GEMM_SMEM);

    // weight transposes -> [N,K] (B col-major for mma .col operand)
    const dim3 tb(32, 8);
    transpose_batched<<<dim3(Dc / 32, Dc / 32, Lc), tb>>>(Wk, pwkT, Dc, Dc);
    transpose_batched<<<dim3(Dc / 32, Dc / 32, Lc), tb>>>(Wv, pwvT, Dc, Dc);
    transpose_batched<<<dim3(Dc / 32, Dc / 32, Lc), tb>>>(Wo, pwoT, Dc, Dc);
    transpose_batched<<<dim3(FFc / 32, Dc / 32, Lc), tb>>>(W1, pw1T, Dc, FFc);
    transpose_batched<<<dim3(Dc / 32, FFc / 32, Lc), tb>>>(W2, pw2T, FFc, Dc);

    const int n4 = M * Dc / 4, sd4 = Sc * Dc / 4;
    add_pos_kernel<<<(n4 + 255) / 256, 256>>>(q_embed,  pos, px, n4, sd4);
    add_pos_kernel<<<(n4 + 255) / 256, 256>>>(qa_embed, pos, py, n4, sd4);

    const dim3 gD(Dc / 128, M / 128);     // N=512 GEMMs
    const dim3 gF(FFc / 128, M / 128);    // N=2048 GEMM

    for (int l = 0; l < Lc; l++) {
        gemm_mma<false><<<gD, 256, GEMM_SMEM>>>(px,  pwkT + (size_t)l * Dc * Dc,  bk + l * Dc,  pqk, Dc, Dc);
        gemm_mma<false><<<gD, 256, GEMM_SMEM>>>(py,  pwvT + (size_t)l * Dc * Dc,  bv + l * Dc,  pv,  Dc, Dc);
        attn_mma<<<dim3(Sc / 64, Bc * Hc), 256, ATTN_SMEM>>>(pqk, pv, forget, pctx);
        gemm_mma<false><<<gD, 256, GEMM_SMEM>>>(pctx, pwoT + (size_t)l * Dc * Dc, bo + l * Dc, pt,  Dc, Dc);
        resid_ln_kernel<<<M, 128>>>(px, pt, g1 + l * Dc, be1 + l * Dc, px);
        gemm_mma<true ><<<gF, 256, GEMM_SMEM>>>(px, pw1T + (size_t)l * FFc * Dc, b1 + l * FFc, pt,  FFc, Dc);
        gemm_mma<false><<<gD, 256, GEMM_SMEM>>>(pt, pw2T + (size_t)l * Dc * FFc, b2 + l * Dc,  pctx, Dc, FFc);
        resid_ln_kernel<<<M, 128>>>(px, pctx, g2 + l * Dc, be2 + l * Dc,
                                    (l == Lc - 1) ? out : px);
    }
}